// round 13
// baseline (speedup 1.0000x reference)
#include <cuda_runtime.h>

static constexpr int B = 4096;
static constexpr int K = 1024;
static constexpr int C = 10;
static constexpr int M = 19;

// b-per-lane: warp = 32 consecutive b (full 128B lines per idx load).
// Block = 32 b x 8 kc = 256 threads; KSPLIT=4 -> grid (128,4)=512, one wave.
static constexpr int NB      = 32;
static constexpr int NC      = 8;
static constexpr int THREADS = NB * NC;           // 256
static constexpr int KSPLIT  = 4;
static constexpr int KBLK    = K / KSPLIT;        // 256
static constexpr int KCHUNK  = KBLK / NC;         // 32 samples per thread

static constexpr int TSTR    = 101;               // table row stride
static constexpr int RSTR    = 257;               // reduce-buffer stride (conflict-free)
static constexpr int POOL_F  = M * RSTR;          // 4883 floats (table needs 3232 < this)

__device__ float g_scratch[B * M];    // zero-init; re-zeroed by finishing block
__device__ int   g_ticket[B / NB];    // zero-init; reset by finishing block

__global__ __launch_bounds__(THREADS, 4)
void ised_kernel(const float* __restrict__ x1,
                 const float* __restrict__ x2,
                 const int*   __restrict__ idx1,
                 const int*   __restrict__ idx2,
                 float*       __restrict__ out)
{
    __shared__ float pool[POOL_F];      // phase 1: product table [bl*101+cell]
                                        // phase 2: reduce buffer [m*257+tid]
    __shared__ float rowsum[NB][M + 1];
    __shared__ int   s_last;

    const int tid = threadIdx.x;
    const int b0  = blockIdx.x * NB;
    const int k0  = blockIdx.y * KBLK;

    // ---- Phase 1 table: pool[bl*101 + i*10 + j] = x1[b,i]*x2[b,j] ----
    for (int e = tid; e < NB * 100; e += THREADS) {
        const int bl = e / 100;
        const int ij = e - bl * 100;
        const int i  = ij / 10;
        const int j  = ij - i * 10;
        pool[bl * TSTR + ij] = __ldg(&x1[(b0 + bl) * C + i]) *
                               __ldg(&x2[(b0 + bl) * C + j]);
    }
    __syncthreads();

    // ---- Main loop: REGISTER bins, predicated select accumulation ----
    const int bl = tid & (NB - 1);
    const int kc = tid >> 5;
    const int b  = b0 + bl;

    const int* __restrict__ p1 = idx1 + (size_t)(k0 + kc * KCHUNK) * B + b;
    const int* __restrict__ p2 = idx2 + (size_t)(k0 + kc * KCHUNK) * B + b;
    const float* __restrict__ myt = pool + bl * TSTR;

    float s[M];
    #pragma unroll
    for (int m = 0; m < M; m++) s[m] = 0.0f;

    #pragma unroll 2
    for (int k = 0; k < KCHUNK; k += 2) {
        // batch 4 loads (2 samples) for MLP
        const int i1a = __ldg(&p1[(size_t)k * B]);
        const int i2a = __ldg(&p2[(size_t)k * B]);
        const int i1b = __ldg(&p1[(size_t)(k + 1) * B]);
        const int i2b = __ldg(&p2[(size_t)(k + 1) * B]);

        const float pa = myt[i1a * 10 + i2a];
        const float pb = myt[i1b * 10 + i2b];
        const int   oa = i1a + i2a;
        const int   ob = i1b + i2b;

        #pragma unroll
        for (int m = 0; m < M; m++) {
            // branch-free: ISETP + SEL + FADD per term; chains independent per m
            s[m] += (oa == m) ? pa : 0.0f;
            s[m] += (ob == m) ? pb : 0.0f;
        }
    }
    __syncthreads();   // table no longer needed; pool becomes reduce buffer

    // ---- Dump register bins: pool[m*257 + tid] (conflict-free: same m/lane) ----
    #pragma unroll
    for (int m = 0; m < M; m++) {
        pool[m * RSTR + tid] = s[m];
    }
    __syncthreads();

    // ---- Reduce 8 kc-partials per (bl, m); push to L2 scratch ----
    for (int e = tid; e < NB * M; e += THREADS) {
        const int rbl = e & (NB - 1);
        const int m   = e >> 5;
        float v = 0.0f;
        #pragma unroll
        for (int c2 = 0; c2 < NC; c2++) {
            v += pool[m * RSTR + c2 * NB + rbl];
        }
        atomicAdd(&g_scratch[(b0 + rbl) * M + m], v);
    }

    // ---- Ticket: last KSPLIT-block for this row-group finishes the rows ----
    __threadfence();
    __syncthreads();
    if (tid == 0) {
        s_last = (atomicAdd(&g_ticket[blockIdx.x], 1) == KSPLIT - 1);
    }
    __syncthreads();
    if (!s_last) return;

    for (int e = tid; e < NB * M; e += THREADS) {
        const int rbl = e & (NB - 1);
        const int m   = e >> 5;
        rowsum[rbl][m] = __ldcg(&g_scratch[(b0 + rbl) * M + m]);
    }
    __syncthreads();

    if (tid < NB) {
        float sq = 0.0f;
        #pragma unroll
        for (int m = 0; m < M; m++) {
            const float v = rowsum[tid][m];
            sq += v * v;
        }
        rowsum[tid][M] = 1.0f / fmaxf(sqrtf(sq), 1e-12f);
    }
    __syncthreads();

    for (int e = tid; e < NB * M; e += THREADS) {
        const int rbl = e & (NB - 1);
        const int m   = e >> 5;
        out[(size_t)(b0 + rbl) * M + m] = rowsum[rbl][m] * rowsum[rbl][M];
        __stcg(&g_scratch[(b0 + rbl) * M + m], 0.0f);   // reset for next replay
    }
    if (tid == 0) {
        g_ticket[blockIdx.x] = 0;
    }
}

extern "C" void kernel_launch(void* const* d_in, const int* in_sizes, int n_in,
                              void* d_out, int out_size)
{
    const float* x1   = (const float*)d_in[0];   // [B, C]
    const float* x2   = (const float*)d_in[1];   // [B, C]
    const int*   idx1 = (const int*)d_in[2];     // [K, B]
    const int*   idx2 = (const int*)d_in[3];     // [K, B]
    float*       out  = (float*)d_out;           // [B, M]

    (void)in_sizes; (void)n_in; (void)out_size;

    dim3 grid(B / NB, KSPLIT);
    ised_kernel<<<grid, THREADS>>>(x1, x2, idx1, idx2, out);
}

// round 14
// speedup vs baseline: 1.6502x; 1.6502x over previous
#include <cuda_runtime.h>

static constexpr int B = 4096;
static constexpr int K = 1024;
static constexpr int C = 10;
static constexpr int M = 19;

// b-per-lane: warp = 32 consecutive b -> every idx load is one full 128B line.
// Block = 32 b x 8 warps; each warp walks its own k-chunk of this block's K-slice.
static constexpr int NB      = 32;
static constexpr int NW      = 8;                 // warps per block
static constexpr int THREADS = NW * 32;           // 256
static constexpr int KSPLIT  = 4;
static constexpr int KBLK    = K / KSPLIT;        // 256
static constexpr int KCHUNK  = KBLK / NW;         // 32 samples per thread

static constexpr int CSTR    = 101;               // cnt row stride (odd -> spread banks)

__device__ float g_scratch[B * M];    // zero-init; re-zeroed by finishing block
__device__ int   g_ticket[B / NB];    // zero-init; reset by finishing block

__global__ __launch_bounds__(THREADS, 4)
void ised_kernel(const float* __restrict__ x1,
                 const float* __restrict__ x2,
                 const int*   __restrict__ idx1,
                 const int*   __restrict__ idx2,
                 float*       __restrict__ out)
{
    __shared__ unsigned cnt[NB * CSTR];   // per-b 10x10 cell histogram (12.9KB)
    __shared__ float    xs1[NB][C];       // x1 rows for this block's 32 b
    __shared__ float    xs2[NB][C];
    __shared__ float    rowsum[NB][M + 1];
    __shared__ int      s_last;

    const int tid = threadIdx.x;
    const int b0  = blockIdx.x * NB;
    const int k0  = blockIdx.y * KBLK;

    // ---- Zero histogram; stage x1/x2 rows ----
    for (int e = tid; e < NB * CSTR; e += THREADS) {
        cnt[e] = 0u;
    }
    for (int e = tid; e < NB * C; e += THREADS) {
        const int bl = e / C;
        const int i  = e - bl * C;
        xs1[bl][i] = __ldg(&x1[(b0 + bl) * C + i]);
        xs2[bl][i] = __ldg(&x2[(b0 + bl) * C + i]);
    }
    __syncthreads();

    // ---- Hot loop: pure histogram via fire-and-forget smem atomics ----
    const int lane = tid & 31;
    const int w    = tid >> 5;
    const int b    = b0 + lane;

    const int* __restrict__ p1 = idx1 + (size_t)(k0 + w * KCHUNK) * B + b;
    const int* __restrict__ p2 = idx2 + (size_t)(k0 + w * KCHUNK) * B + b;
    unsigned* __restrict__ myc = cnt + lane * CSTR;

    #pragma unroll 4
    for (int k = 0; k < KCHUNK; k++) {
        const int i1 = __ldg(&p1[(size_t)k * B]);
        const int i2 = __ldg(&p2[(size_t)k * B]);
        atomicAdd(&myc[i1 * 10 + i2], 1u);   // RED.shared: no RMW chain, no wait
    }
    __syncthreads();

    // ---- Epilogue: result[b][m] = sum_{i+j=m} xs1[i]*xs2[j]*cnt[i,j] ----
    for (int e = tid; e < NB * M; e += THREADS) {
        const int bl = e & (NB - 1);
        const int m  = e >> 5;
        const int ilo = (m > 9) ? (m - 9) : 0;
        const int ihi = (m < 9) ? m : 9;
        float v = 0.0f;
        for (int i = ilo; i <= ihi; i++) {
            const int j = m - i;
            v += xs1[bl][i] * xs2[bl][j] *
                 (float)cnt[bl * CSTR + i * 10 + j];
        }
        atomicAdd(&g_scratch[(b0 + bl) * M + m], v);
    }

    // ---- Ticket: last KSPLIT-block for this row-group finishes the rows ----
    __threadfence();
    __syncthreads();
    if (tid == 0) {
        s_last = (atomicAdd(&g_ticket[blockIdx.x], 1) == KSPLIT - 1);
    }
    __syncthreads();
    if (!s_last) return;

    for (int e = tid; e < NB * M; e += THREADS) {
        const int bl = e & (NB - 1);
        const int m  = e >> 5;
        rowsum[bl][m] = __ldcg(&g_scratch[(b0 + bl) * M + m]);
    }
    __syncthreads();

    if (tid < NB) {
        float sq = 0.0f;
        #pragma unroll
        for (int m = 0; m < M; m++) {
            const float v = rowsum[tid][m];
            sq += v * v;
        }
        rowsum[tid][M] = 1.0f / fmaxf(sqrtf(sq), 1e-12f);
    }
    __syncthreads();

    for (int e = tid; e < NB * M; e += THREADS) {
        const int bl = e & (NB - 1);
        const int m  = e >> 5;
        out[(size_t)(b0 + bl) * M + m] = rowsum[bl][m] * rowsum[bl][M];
        __stcg(&g_scratch[(b0 + bl) * M + m], 0.0f);   // reset for next replay
    }
    if (tid == 0) {
        g_ticket[blockIdx.x] = 0;
    }
}

extern "C" void kernel_launch(void* const* d_in, const int* in_sizes, int n_in,
                              void* d_out, int out_size)
{
    const float* x1   = (const float*)d_in[0];   // [B, C]
    const float* x2   = (const float*)d_in[1];   // [B, C]
    const int*   idx1 = (const int*)d_in[2];     // [K, B]
    const int*   idx2 = (const int*)d_in[3];     // [K, B]
    float*       out  = (float*)d_out;           // [B, M]

    (void)in_sizes; (void)n_in; (void)out_size;

    dim3 grid(B / NB, KSPLIT);
    ised_kernel<<<grid, THREADS>>>(x1, x2, idx1, idx2, out);
}